// round 4
// baseline (speedup 1.0000x reference)
#include <cuda_runtime.h>
#include <cuda_bf16.h>
#include <math.h>
#include <stdint.h>

#define BB   128
#define CF   1024
#define RR   256
#define NATT 312
#define DV   300
#define NI   624
#define NIP  640

// ---------------- scratch (device globals) ----------------
__device__ float         g_vv[NATT * DV];
__device__ __nv_bfloat16 g_Ah[NIP * CF];              // interleaved [2i]=Q_i,[2i+1]=P_i
__device__ __nv_bfloat16 g_Al[NIP * CF];
__device__ __nv_bfloat16 g_Bh[(size_t)BB * RR * CF];  // [b][r][k] normalized, hi
__device__ __nv_bfloat16 g_Bl[(size_t)BB * RR * CF];  // lo
__device__ float         g_inorm[BB * RR];

// ---------------- helpers ----------------
__device__ __forceinline__ uint32_t smem_u32(const void* p) {
    uint32_t a;
    asm("{ .reg .u64 t; cvta.to.shared.u64 t, %1; cvt.u32.u64 %0, t; }" : "=r"(a) : "l"(p));
    return a;
}
#define CP_ASYNC16(dst, src) \
    asm volatile("cp.async.cg.shared.global [%0], [%1], 16;" :: "r"(dst), "l"(src) : "memory")
#define CP_COMMIT() asm volatile("cp.async.commit_group;" ::: "memory")
#define CP_WAIT(N)  asm volatile("cp.async.wait_group %0;" :: "n"(N) : "memory")

__device__ __forceinline__ void ldsm4(uint32_t* r, uint32_t addr) {
    asm volatile("ldmatrix.sync.aligned.m8n8.x4.shared.b16 {%0,%1,%2,%3}, [%4];"
                 : "=r"(r[0]), "=r"(r[1]), "=r"(r[2]), "=r"(r[3]) : "r"(addr));
}
__device__ __forceinline__ void mma_bf16(float* c, const uint32_t* a, const uint32_t* b) {
    asm volatile(
        "mma.sync.aligned.m16n8k16.row.col.f32.bf16.bf16.f32 "
        "{%0,%1,%2,%3}, {%4,%5,%6,%7}, {%8,%9}, {%0,%1,%2,%3};"
        : "+f"(c[0]), "+f"(c[1]), "+f"(c[2]), "+f"(c[3])
        : "r"(a[0]), "r"(a[1]), "r"(a[2]), "r"(a[3]), "r"(b[0]), "r"(b[1]));
}

// ---------------------------------------------------------------------------
// 1) vv = l2norm(V, axis=1)
// ---------------------------------------------------------------------------
__global__ void k_vnorm(const float* __restrict__ V) {
    int i = blockIdx.x;
    __shared__ float red[128];
    float s = 0.f;
    for (int k = threadIdx.x; k < DV; k += 128) { float v = V[i * DV + k]; s += v * v; }
    red[threadIdx.x] = s; __syncthreads();
    for (int off = 64; off; off >>= 1) {
        if (threadIdx.x < off) red[threadIdx.x] += red[threadIdx.x + off];
        __syncthreads();
    }
    float inv = 1.f / fmaxf(sqrtf(red[0]), 1e-12f);
    for (int k = threadIdx.x; k < DV; k += 128) g_vv[i * DV + k] = V[i * DV + k] * inv;
}

// ---------------------------------------------------------------------------
// 2) QP rows, interleaved, hi/lo bf16 split. grid (39, 4, 2)
// ---------------------------------------------------------------------------
__global__ void __launch_bounds__(256) k_qp(const float* __restrict__ W1,
                                            const float* __restrict__ W2) {
    int i0 = blockIdx.x * 8;
    int z  = blockIdx.z;
    const float* W = z ? W2 : W1;
    __shared__ float vrow[8][DV];
    for (int t = threadIdx.x; t < 8 * DV; t += 256) {
        int ii = t / DV, k = t % DV;
        vrow[ii][k] = g_vv[(i0 + ii) * DV + k];
    }
    __syncthreads();
    int j = blockIdx.y * 256 + threadIdx.x;
    float acc[8] = {0,0,0,0,0,0,0,0};
    for (int k = 0; k < DV; k++) {
        float w = W[k * CF + j];
#pragma unroll
        for (int ii = 0; ii < 8; ii++) acc[ii] += vrow[ii][k] * w;
    }
#pragma unroll
    for (int ii = 0; ii < 8; ii++) {
        int row = 2 * (i0 + ii) + z;
        float x = acc[ii];
        __nv_bfloat16 h = __float2bfloat16(x);
        __nv_bfloat16 l = __float2bfloat16(x - __bfloat162float(h));
        g_Ah[row * CF + j] = h;
        g_Al[row * CF + j] = l;
    }
}

__global__ void k_padA() {
    int t = blockIdx.x * 256 + threadIdx.x;
    if (t < (NIP - NI) * CF) {
        g_Ah[NI * CF + t] = __float2bfloat16(0.f);
        g_Al[NI * CF + t] = __float2bfloat16(0.f);
    }
}

// ---------------------------------------------------------------------------
// 3) inverse column norms
// ---------------------------------------------------------------------------
__global__ void __launch_bounds__(1024) k_nsq(const float* __restrict__ img) {
    int b = blockIdx.x;
    int r = threadIdx.x & 255;
    int q = threadIdx.x >> 8;
    const float* p = img + (size_t)b * CF * RR + r;
    float s = 0.f;
#pragma unroll 8
    for (int f = q * 256; f < q * 256 + 256; f++) { float v = p[(size_t)f * RR]; s += v * v; }
    __shared__ float red[1024];
    red[threadIdx.x] = s; __syncthreads();
    if (q == 0) {
        s = red[r] + red[r + 256] + red[r + 512] + red[r + 768];
        g_inorm[b * RR + r] = 1.f / fmaxf(sqrtf(s), 1e-12f);
    }
}

// ---------------------------------------------------------------------------
// 4) transpose + normalize + hi/lo convert
// ---------------------------------------------------------------------------
__global__ void __launch_bounds__(256) k_bt(const float* __restrict__ img) {
    int b  = blockIdx.z;
    int k0 = blockIdx.y * 32;
    int r0 = blockIdx.x * 32;
    __shared__ float t[32][33];
    const float* src = img + (size_t)b * CF * RR;
#pragma unroll
    for (int d = 0; d < 4; d++) {
        int ky = threadIdx.y + 8 * d;
        t[ky][threadIdx.x] = src[(size_t)(k0 + ky) * RR + r0 + threadIdx.x];
    }
    __syncthreads();
#pragma unroll
    for (int d = 0; d < 4; d++) {
        int ry = threadIdx.y + 8 * d;
        int r = r0 + ry;
        float s = g_inorm[b * RR + r];
        float v = t[threadIdx.x][ry] * s;
        __nv_bfloat16 h = __float2bfloat16(v);
        __nv_bfloat16 l = __float2bfloat16(v - __bfloat162float(h));
        size_t o = ((size_t)b * RR + r) * CF + k0 + threadIdx.x;
        g_Bh[o] = h;
        g_Bl[o] = l;
    }
}

// ---------------------------------------------------------------------------
// 5) warp-MMA GEMM (3-term bf16) + fused softmax-dot epilogue.
//    CTA: M=128, N=256, K chunks of 32, 3-stage cp.async pipeline.
//    grid (5 itiles, 128 b), 256 threads (8 warps, 2x4, warp tile 64x64).
// ---------------------------------------------------------------------------
#define KC     32
#define NCH    (CF / KC)       // 32
#define SROW   80              // KC*2 + 16B pad
#define A_H    0
#define A_L    10240           // 128*80
#define B_H    20480
#define B_L    40960           // +256*80
#define STG    61440
#define NSTAGE 3
#define SMEM_DYN (NSTAGE * STG)   // 184320
#define CSTRIDE 264

__global__ void __launch_bounds__(256, 1) k_gemm_mma(float* __restrict__ out) {
    extern __shared__ __align__(128) char dsm[];
    const int tid   = threadIdx.x;
    const int wid   = tid >> 5;
    const int lane  = tid & 31;
    const int itile = blockIdx.x;
    const int b     = blockIdx.y;
    const int mw    = wid >> 2;           // 0..1
    const int nw    = wid & 3;            // 0..3

    const uint32_t sbase = smem_u32(dsm);

    const char* pAh = (const char*)g_Ah + (size_t)(itile * 128) * CF * 2;
    const char* pAl = (const char*)g_Al + (size_t)(itile * 128) * CF * 2;
    const char* pBh = (const char*)g_Bh + (size_t)b * RR * CF * 2;
    const char* pBl = (const char*)g_Bl + (size_t)b * RR * CF * 2;

    // cp.async mapping: idx = tid + it*256; row = idx>>2; j = idx&3
    const int crow = tid >> 2, cj = tid & 3;

    // ldmatrix A: 16x16 tiles. lanes 0-15: m rows, k low 16B; 16-31: k high 16B
    const uint32_t aoff = (uint32_t)((mw * 64 + (lane & 15)) * SROW + ((lane >> 4) << 4));
    // ldmatrix B x4 spanning two n8-blocks:
    // lanes 0-7: n row (lane&7), k low; 8-15: same n rows, k high;
    // 16-23: n+8 rows, k low; 24-31: n+8 rows, k high
    const uint32_t boff = (uint32_t)((nw * 64 + ((lane >> 4) << 3) + (lane & 7)) * SROW
                                     + (((lane >> 3) & 1) << 4));

    float acc[4][8][4];
#pragma unroll
    for (int mi = 0; mi < 4; mi++)
#pragma unroll
        for (int ni = 0; ni < 8; ni++)
#pragma unroll
            for (int u = 0; u < 4; u++) acc[mi][ni][u] = 0.f;

    auto load_chunk = [&](int buf, int c) {
        const size_t kb = (size_t)c * (KC * 2);
        const uint32_t st = sbase + buf * STG;
        // A: 128 rows x 64B, hi+lo: 2 iters each
#pragma unroll
        for (int it = 0; it < 2; it++) {
            int row = crow + it * 64;
            CP_ASYNC16(st + A_H + row * SROW + cj * 16,
                       pAh + (size_t)row * (CF * 2) + kb + cj * 16);
            CP_ASYNC16(st + A_L + row * SROW + cj * 16,
                       pAl + (size_t)row * (CF * 2) + kb + cj * 16);
        }
        // B: 256 rows x 64B, hi+lo: 4 iters each
#pragma unroll
        for (int it = 0; it < 4; it++) {
            int row = crow + it * 64;
            CP_ASYNC16(st + B_H + row * SROW + cj * 16,
                       pBh + (size_t)row * (CF * 2) + kb + cj * 16);
            CP_ASYNC16(st + B_L + row * SROW + cj * 16,
                       pBl + (size_t)row * (CF * 2) + kb + cj * 16);
        }
    };

    load_chunk(0, 0); CP_COMMIT();
    load_chunk(1, 1); CP_COMMIT();

    for (int c = 0; c < NCH; c++) {
        const int buf = c % NSTAGE;
        if (c + 2 < NCH) {
            load_chunk((c + 2) % NSTAGE, c + 2); CP_COMMIT();
            CP_WAIT(2);
        } else if (c + 1 < NCH) {
            CP_WAIT(1);
        } else {
            CP_WAIT(0);
        }
        __syncthreads();

        const uint32_t st = sbase + buf * STG;
#pragma unroll
        for (int ks = 0; ks < 2; ks++) {
            const uint32_t kb = ks * 32;   // 16 bf16 = 32 bytes
            uint32_t ah[4][4], al[4][4];
#pragma unroll
            for (int mi = 0; mi < 4; mi++) {
                ldsm4(ah[mi], st + A_H + aoff + mi * (16 * SROW) + kb);
                ldsm4(al[mi], st + A_L + aoff + mi * (16 * SROW) + kb);
            }
#pragma unroll
            for (int p = 0; p < 4; p++) {        // n8-block pairs
                uint32_t bh4[4], bl4[4];
                ldsm4(bh4, st + B_H + boff + p * (16 * SROW) + kb);
                ldsm4(bl4, st + B_L + boff + p * (16 * SROW) + kb);
#pragma unroll
                for (int mi = 0; mi < 4; mi++) {
                    mma_bf16(acc[mi][2 * p],     ah[mi], bh4);
                    mma_bf16(acc[mi][2 * p],     ah[mi], bl4);
                    mma_bf16(acc[mi][2 * p],     al[mi], bh4);
                    mma_bf16(acc[mi][2 * p + 1], ah[mi], bh4 + 2);
                    mma_bf16(acc[mi][2 * p + 1], ah[mi], bl4 + 2);
                    mma_bf16(acc[mi][2 * p + 1], al[mi], bh4 + 2);
                }
            }
        }
        __syncthreads();
    }

    // ---- epilogue: accums -> smem C[128][CSTRIDE] ----
    float* Cs = (float*)dsm;
    const int n0 = nw * 64;
#pragma unroll
    for (int mi = 0; mi < 4; mi++)
#pragma unroll
        for (int ni = 0; ni < 8; ni++) {
            int r0 = mw * 64 + mi * 16 + (lane >> 2);
            int c0 = n0 + ni * 8 + 2 * (lane & 3);
            Cs[r0 * CSTRIDE + c0]           = acc[mi][ni][0];
            Cs[r0 * CSTRIDE + c0 + 1]       = acc[mi][ni][1];
            Cs[(r0 + 8) * CSTRIDE + c0]     = acc[mi][ni][2];
            Cs[(r0 + 8) * CSTRIDE + c0 + 1] = acc[mi][ni][3];
        }
    __syncthreads();

    // ---- softmax-dot: 64 row-pairs, 8 per warp ----
#pragma unroll
    for (int pp = 0; pp < 8; pp++) {
        int p = wid * 8 + pp;                  // 0..63
        const float* r1 = Cs + (2 * p) * CSTRIDE;
        const float* r2 = Cs + (2 * p + 1) * CSTRIDE;
        float l1[8], l2[8];
        float m = -INFINITY;
#pragma unroll
        for (int u = 0; u < 8; u++) {
            int r = lane + u * 32;
            l1[u] = r1[r];
            l2[u] = r2[r];
            m = fmaxf(m, l1[u]);
        }
#pragma unroll
        for (int off = 16; off; off >>= 1)
            m = fmaxf(m, __shfl_xor_sync(0xffffffffu, m, off));
        float se = 0.f, sd = 0.f;
#pragma unroll
        for (int u = 0; u < 8; u++) {
            float e = __expf(l1[u] - m);
            se += e;
            sd += e * l2[u];
        }
#pragma unroll
        for (int off = 16; off; off >>= 1) {
            se += __shfl_xor_sync(0xffffffffu, se, off);
            sd += __shfl_xor_sync(0xffffffffu, sd, off);
        }
        int i = itile * 64 + p;
        if (lane == 0 && i < NATT) out[b * NATT + i] = sd / se;
    }
}

// ---------------------------------------------------------------------------
extern "C" void kernel_launch(void* const* d_in, const int* in_sizes, int n_in,
                              void* d_out, int out_size) {
    const float* img = (const float*)d_in[0];
    const float* V   = (const float*)d_in[1];
    const float* W1  = (const float*)d_in[2];
    const float* W2  = (const float*)d_in[3];
    float* out = (float*)d_out;

    cudaFuncSetAttribute(k_gemm_mma, cudaFuncAttributeMaxDynamicSharedMemorySize, SMEM_DYN);

    k_vnorm<<<NATT, 128>>>(V);
    k_qp<<<dim3(NATT / 8, CF / 256, 2), 256>>>(W1, W2);
    k_padA<<<((NIP - NI) * CF + 255) / 256, 256>>>();
    k_nsq<<<BB, 1024>>>(img);
    k_bt<<<dim3(RR / 32, CF / 32, BB), dim3(32, 8)>>>(img);
    k_gemm_mma<<<dim3(5, BB), 256, SMEM_DYN>>>(out);
}

// round 5
// speedup vs baseline: 1.2429x; 1.2429x over previous
#include <cuda_runtime.h>
#include <cuda_fp16.h>
#include <math.h>
#include <stdint.h>

#define BB   128
#define CF   1024
#define RR   256
#define NATT 312
#define DV   300
#define NI   624
#define NIP  640

// ---------------- scratch (device globals) ----------------
__device__ __half g_Ah[NIP * CF];              // interleaved [2i]=Q_i,[2i+1]=P_i (hi)
__device__ __half g_Al[NIP * CF];              // (lo residual)
__device__ __half g_B[(size_t)BB * RR * CF];   // [b][r][k] normalized, single fp16
__device__ float  g_inorm[BB * RR];

// ---------------- helpers ----------------
__device__ __forceinline__ uint32_t smem_u32(const void* p) {
    uint32_t a;
    asm("{ .reg .u64 t; cvta.to.shared.u64 t, %1; cvt.u32.u64 %0, t; }" : "=r"(a) : "l"(p));
    return a;
}
#define CP_ASYNC16(dst, src) \
    asm volatile("cp.async.cg.shared.global [%0], [%1], 16;" :: "r"(dst), "l"(src) : "memory")
#define CP_COMMIT() asm volatile("cp.async.commit_group;" ::: "memory")
#define CP_WAIT(N)  asm volatile("cp.async.wait_group %0;" :: "n"(N) : "memory")

__device__ __forceinline__ void ldsm4(uint32_t* r, uint32_t addr) {
    asm volatile("ldmatrix.sync.aligned.m8n8.x4.shared.b16 {%0,%1,%2,%3}, [%4];"
                 : "=r"(r[0]), "=r"(r[1]), "=r"(r[2]), "=r"(r[3]) : "r"(addr));
}
__device__ __forceinline__ void mma_fp16(float* c, const uint32_t* a, const uint32_t* b) {
    asm volatile(
        "mma.sync.aligned.m16n8k16.row.col.f32.f16.f16.f32 "
        "{%0,%1,%2,%3}, {%4,%5,%6,%7}, {%8,%9}, {%0,%1,%2,%3};"
        : "+f"(c[0]), "+f"(c[1]), "+f"(c[2]), "+f"(c[3])
        : "r"(a[0]), "r"(a[1]), "r"(a[2]), "r"(a[3]), "r"(b[0]), "r"(b[1]));
}

// ---------------------------------------------------------------------------
// 1) QP rows: normalize V rows in-block, multiply by W, interleave, fp16 hi/lo.
//    grid (40, 4, 2): block x=39 handles zero-padding rows 624..639.
// ---------------------------------------------------------------------------
__global__ void __launch_bounds__(256) k_qp(const float* __restrict__ V,
                                            const float* __restrict__ W1,
                                            const float* __restrict__ W2) {
    int i0 = blockIdx.x * 8;
    int z  = blockIdx.z;
    int j  = blockIdx.y * 256 + threadIdx.x;

    if (i0 >= NATT) {  // padding rows
#pragma unroll
        for (int ii = 0; ii < 8; ii++) {
            int row = 2 * (i0 + ii) + z;
            g_Ah[row * CF + j] = __float2half(0.f);
            g_Al[row * CF + j] = __float2half(0.f);
        }
        return;
    }

    const float* W = z ? W2 : W1;
    __shared__ float vrow[8][DV];
    for (int t = threadIdx.x; t < 8 * DV; t += 256) {
        int ii = t / DV, k = t % DV;
        vrow[ii][k] = V[(i0 + ii) * DV + k];
    }
    __syncthreads();
    // warp w normalizes row w
    {
        int w = threadIdx.x >> 5, lane = threadIdx.x & 31;
        float s = 0.f;
        for (int k = lane; k < DV; k += 32) { float v = vrow[w][k]; s += v * v; }
#pragma unroll
        for (int off = 16; off; off >>= 1) s += __shfl_xor_sync(0xffffffffu, s, off);
        float inv = 1.f / fmaxf(sqrtf(s), 1e-12f);
        for (int k = lane; k < DV; k += 32) vrow[w][k] *= inv;
    }
    __syncthreads();

    float acc[8] = {0,0,0,0,0,0,0,0};
    for (int k = 0; k < DV; k++) {
        float w = W[k * CF + j];
#pragma unroll
        for (int ii = 0; ii < 8; ii++) acc[ii] += vrow[ii][k] * w;
    }
#pragma unroll
    for (int ii = 0; ii < 8; ii++) {
        int row = 2 * (i0 + ii) + z;
        float x = acc[ii];
        __half h = __float2half(x);
        __half l = __float2half(x - __half2float(h));
        g_Ah[row * CF + j] = h;
        g_Al[row * CF + j] = l;
    }
}

// ---------------------------------------------------------------------------
// 2) inverse column norms
// ---------------------------------------------------------------------------
__global__ void __launch_bounds__(1024) k_nsq(const float* __restrict__ img) {
    int b = blockIdx.x;
    int r = threadIdx.x & 255;
    int q = threadIdx.x >> 8;
    const float* p = img + (size_t)b * CF * RR + r;
    float s = 0.f;
#pragma unroll 8
    for (int f = q * 256; f < q * 256 + 256; f++) { float v = p[(size_t)f * RR]; s += v * v; }
    __shared__ float red[1024];
    red[threadIdx.x] = s; __syncthreads();
    if (q == 0) {
        s = red[r] + red[r + 256] + red[r + 512] + red[r + 768];
        g_inorm[b * RR + r] = 1.f / fmaxf(sqrtf(s), 1e-12f);
    }
}

// ---------------------------------------------------------------------------
// 3) transpose + normalize + fp16 convert (single array)
// ---------------------------------------------------------------------------
__global__ void __launch_bounds__(256) k_bt(const float* __restrict__ img) {
    int b  = blockIdx.z;
    int k0 = blockIdx.y * 32;
    int r0 = blockIdx.x * 32;
    __shared__ float t[32][33];
    const float* src = img + (size_t)b * CF * RR;
#pragma unroll
    for (int d = 0; d < 4; d++) {
        int ky = threadIdx.y + 8 * d;
        t[ky][threadIdx.x] = src[(size_t)(k0 + ky) * RR + r0 + threadIdx.x];
    }
    __syncthreads();
#pragma unroll
    for (int d = 0; d < 4; d++) {
        int ry = threadIdx.y + 8 * d;
        int r = r0 + ry;
        float s = g_inorm[b * RR + r];
        float v = t[threadIdx.x][ry] * s;
        size_t o = ((size_t)b * RR + r) * CF + k0 + threadIdx.x;
        g_B[o] = __float2half(v);
    }
}

// ---------------------------------------------------------------------------
// 4) warp-MMA GEMM (fp16, 2-term A-split) + fused softmax-dot epilogue.
//    CTA: M=128, N=256, K chunks of 32, 3-stage cp.async pipeline.
//    grid (5 itiles, 128 b), 256 threads (8 warps, 2x4, warp tile 64x64).
// ---------------------------------------------------------------------------
#define KC     32
#define NCH    (CF / KC)        // 32
#define SROW   80               // KC*2 + 16B pad
#define A_H    0
#define A_L    10240            // 128*80
#define B_O    20480
#define STG    40960            // + 256*80
#define NSTAGE 3
#define SMEM_DYN (NSTAGE * STG) // 122880
#define CSTRIDE 264

__global__ void __launch_bounds__(256, 1) k_gemm_mma(float* __restrict__ out) {
    extern __shared__ __align__(128) char dsm[];
    const int tid   = threadIdx.x;
    const int wid   = tid >> 5;
    const int lane  = tid & 31;
    const int itile = blockIdx.x;
    const int b     = blockIdx.y;
    const int mw    = wid >> 2;           // 0..1
    const int nw    = wid & 3;            // 0..3

    const uint32_t sbase = smem_u32(dsm);

    const char* pAh = (const char*)g_Ah + (size_t)(itile * 128) * CF * 2;
    const char* pAl = (const char*)g_Al + (size_t)(itile * 128) * CF * 2;
    const char* pB  = (const char*)g_B  + (size_t)b * RR * CF * 2;

    const int crow = tid >> 2, cj = tid & 3;

    // ldmatrix A: 16x16 tiles (proven mapping from R3/R4)
    const uint32_t aoff = (uint32_t)((mw * 64 + (lane & 15)) * SROW + ((lane >> 4) << 4));
    // ldmatrix B x4 spanning two n8-blocks (proven mapping)
    const uint32_t boff = (uint32_t)((nw * 64 + ((lane >> 4) << 3) + (lane & 7)) * SROW
                                     + (((lane >> 3) & 1) << 4));

    float acc[4][8][4];
#pragma unroll
    for (int mi = 0; mi < 4; mi++)
#pragma unroll
        for (int ni = 0; ni < 8; ni++)
#pragma unroll
            for (int u = 0; u < 4; u++) acc[mi][ni][u] = 0.f;

    auto load_chunk = [&](int buf, int c) {
        const size_t kb = (size_t)c * (KC * 2);
        const uint32_t st = sbase + buf * STG;
#pragma unroll
        for (int it = 0; it < 2; it++) {
            int row = crow + it * 64;
            CP_ASYNC16(st + A_H + row * SROW + cj * 16,
                       pAh + (size_t)row * (CF * 2) + kb + cj * 16);
            CP_ASYNC16(st + A_L + row * SROW + cj * 16,
                       pAl + (size_t)row * (CF * 2) + kb + cj * 16);
        }
#pragma unroll
        for (int it = 0; it < 4; it++) {
            int row = crow + it * 64;
            CP_ASYNC16(st + B_O + row * SROW + cj * 16,
                       pB + (size_t)row * (CF * 2) + kb + cj * 16);
        }
    };

    load_chunk(0, 0); CP_COMMIT();
    load_chunk(1, 1); CP_COMMIT();

    for (int c = 0; c < NCH; c++) {
        const int buf = c % NSTAGE;
        if (c + 2 < NCH) {
            load_chunk((c + 2) % NSTAGE, c + 2); CP_COMMIT();
            CP_WAIT(2);
        } else if (c + 1 < NCH) {
            CP_WAIT(1);
        } else {
            CP_WAIT(0);
        }
        __syncthreads();

        const uint32_t st = sbase + buf * STG;
#pragma unroll
        for (int ks = 0; ks < 2; ks++) {
            const uint32_t kb = ks * 32;   // 16 fp16 = 32 bytes
            uint32_t ah[4][4], al[4][4];
#pragma unroll
            for (int mi = 0; mi < 4; mi++) {
                ldsm4(ah[mi], st + A_H + aoff + mi * (16 * SROW) + kb);
                ldsm4(al[mi], st + A_L + aoff + mi * (16 * SROW) + kb);
            }
#pragma unroll
            for (int p = 0; p < 4; p++) {
                uint32_t b4[4];
                ldsm4(b4, st + B_O + boff + p * (16 * SROW) + kb);
#pragma unroll
                for (int mi = 0; mi < 4; mi++) {
                    mma_fp16(acc[mi][2 * p],     ah[mi], b4);
                    mma_fp16(acc[mi][2 * p],     al[mi], b4);
                    mma_fp16(acc[mi][2 * p + 1], ah[mi], b4 + 2);
                    mma_fp16(acc[mi][2 * p + 1], al[mi], b4 + 2);
                }
            }
        }
        __syncthreads();
    }

    // ---- epilogue in 2 halves (Cs = 64 x CSTRIDE floats, fits in pipeline smem) ----
    float* Cs = (float*)dsm;
    const int n0 = nw * 64;
#pragma unroll 1
    for (int h = 0; h < 2; h++) {
        __syncthreads();
        if (mw == h) {
#pragma unroll
            for (int mi = 0; mi < 4; mi++)
#pragma unroll
                for (int ni = 0; ni < 8; ni++) {
                    int r0 = mi * 16 + (lane >> 2);        // local row 0..63
                    int c0 = n0 + ni * 8 + 2 * (lane & 3);
                    Cs[r0 * CSTRIDE + c0]           = acc[mi][ni][0];
                    Cs[r0 * CSTRIDE + c0 + 1]       = acc[mi][ni][1];
                    Cs[(r0 + 8) * CSTRIDE + c0]     = acc[mi][ni][2];
                    Cs[(r0 + 8) * CSTRIDE + c0 + 1] = acc[mi][ni][3];
                }
        }
        __syncthreads();
        // 32 row-pairs in this half, 4 per warp
#pragma unroll
        for (int pp = 0; pp < 4; pp++) {
            int p = wid * 4 + pp;                  // 0..31
            const float* r1 = Cs + (2 * p) * CSTRIDE;
            const float* r2 = Cs + (2 * p + 1) * CSTRIDE;
            float l1[8], l2[8];
            float m = -INFINITY;
#pragma unroll
            for (int u = 0; u < 8; u++) {
                int r = lane + u * 32;
                l1[u] = r1[r];
                l2[u] = r2[r];
                m = fmaxf(m, l1[u]);
            }
#pragma unroll
            for (int off = 16; off; off >>= 1)
                m = fmaxf(m, __shfl_xor_sync(0xffffffffu, m, off));
            float se = 0.f, sd = 0.f;
#pragma unroll
            for (int u = 0; u < 8; u++) {
                float e = __expf(l1[u] - m);
                se += e;
                sd += e * l2[u];
            }
#pragma unroll
            for (int off = 16; off; off >>= 1) {
                se += __shfl_xor_sync(0xffffffffu, se, off);
                sd += __shfl_xor_sync(0xffffffffu, sd, off);
            }
            int i = itile * 64 + h * 32 + p;
            if (lane == 0 && i < NATT) out[b * NATT + i] = sd / se;
        }
    }
}

// ---------------------------------------------------------------------------
extern "C" void kernel_launch(void* const* d_in, const int* in_sizes, int n_in,
                              void* d_out, int out_size) {
    const float* img = (const float*)d_in[0];
    const float* V   = (const float*)d_in[1];
    const float* W1  = (const float*)d_in[2];
    const float* W2  = (const float*)d_in[3];
    float* out = (float*)d_out;

    cudaFuncSetAttribute(k_gemm_mma, cudaFuncAttributeMaxDynamicSharedMemorySize, SMEM_DYN);

    k_qp<<<dim3(40, CF / 256, 2), 256>>>(V, W1, W2);
    k_nsq<<<BB, 1024>>>(img);
    k_bt<<<dim3(RR / 32, CF / 32, BB), dim3(32, 8)>>>(img);
    k_gemm_mma<<<dim3(5, BB), 256, SMEM_DYN>>>(out);
}

// round 6
// speedup vs baseline: 1.3929x; 1.1208x over previous
#include <cuda_runtime.h>
#include <cuda_fp16.h>
#include <math.h>
#include <stdint.h>

#define BB   128
#define CF   1024
#define RR   256
#define NATT 312
#define DV   300
#define NI   624
#define NIP  640

// ---------------- scratch (device globals) ----------------
__device__ __half g_Ah[NIP * CF];              // interleaved [2i]=Q_i,[2i+1]=P_i (hi)
__device__ __half g_Al[NIP * CF];              // (lo residual)
__device__ __half g_B[(size_t)BB * RR * CF];   // [b][r][k] normalized, single fp16
__device__ float  g_inorm[BB * RR];

// ---------------- helpers ----------------
__device__ __forceinline__ uint32_t smem_u32(const void* p) {
    uint32_t a;
    asm("{ .reg .u64 t; cvta.to.shared.u64 t, %1; cvt.u32.u64 %0, t; }" : "=r"(a) : "l"(p));
    return a;
}
#define CP_ASYNC16(dst, src) \
    asm volatile("cp.async.cg.shared.global [%0], [%1], 16;" :: "r"(dst), "l"(src) : "memory")
#define CP_COMMIT() asm volatile("cp.async.commit_group;" ::: "memory")
#define CP_WAIT(N)  asm volatile("cp.async.wait_group %0;" :: "n"(N) : "memory")

__device__ __forceinline__ void ldsm4(uint32_t* r, uint32_t addr) {
    asm volatile("ldmatrix.sync.aligned.m8n8.x4.shared.b16 {%0,%1,%2,%3}, [%4];"
                 : "=r"(r[0]), "=r"(r[1]), "=r"(r[2]), "=r"(r[3]) : "r"(addr));
}
__device__ __forceinline__ void mma_fp16(float* c, const uint32_t* a, const uint32_t* b) {
    asm volatile(
        "mma.sync.aligned.m16n8k16.row.col.f32.f16.f16.f32 "
        "{%0,%1,%2,%3}, {%4,%5,%6,%7}, {%8,%9}, {%0,%1,%2,%3};"
        : "+f"(c[0]), "+f"(c[1]), "+f"(c[2]), "+f"(c[3])
        : "r"(a[0]), "r"(a[1]), "r"(a[2]), "r"(a[3]), "r"(b[0]), "r"(b[1]));
}

// ---------------------------------------------------------------------------
// 1) QP rows: normalize V rows in-block, multiply by W, interleave, fp16 hi/lo.
//    grid (40, 4, 2): block x=39 zero-pads rows 624..639.
// ---------------------------------------------------------------------------
__global__ void __launch_bounds__(256) k_qp(const float* __restrict__ V,
                                            const float* __restrict__ W1,
                                            const float* __restrict__ W2) {
    int i0 = blockIdx.x * 8;
    int z  = blockIdx.z;
    int j  = blockIdx.y * 256 + threadIdx.x;

    if (i0 >= NATT) {
#pragma unroll
        for (int ii = 0; ii < 8; ii++) {
            int row = 2 * (i0 + ii) + z;
            g_Ah[row * CF + j] = __float2half(0.f);
            g_Al[row * CF + j] = __float2half(0.f);
        }
        return;
    }

    const float* W = z ? W2 : W1;
    __shared__ float vrow[8][DV];
    for (int t = threadIdx.x; t < 8 * DV; t += 256) {
        int ii = t / DV, k = t % DV;
        vrow[ii][k] = V[(i0 + ii) * DV + k];
    }
    __syncthreads();
    {
        int w = threadIdx.x >> 5, lane = threadIdx.x & 31;
        float s = 0.f;
        for (int k = lane; k < DV; k += 32) { float v = vrow[w][k]; s += v * v; }
#pragma unroll
        for (int off = 16; off; off >>= 1) s += __shfl_xor_sync(0xffffffffu, s, off);
        float inv = 1.f / fmaxf(sqrtf(s), 1e-12f);
        for (int k = lane; k < DV; k += 32) vrow[w][k] *= inv;
    }
    __syncthreads();

    float acc[8] = {0,0,0,0,0,0,0,0};
    for (int k = 0; k < DV; k++) {
        float w = W[k * CF + j];
#pragma unroll
        for (int ii = 0; ii < 8; ii++) acc[ii] += vrow[ii][k] * w;
    }
#pragma unroll
    for (int ii = 0; ii < 8; ii++) {
        int row = 2 * (i0 + ii) + z;
        float x = acc[ii];
        __half h = __float2half(x);
        __half l = __float2half(x - __half2float(h));
        g_Ah[row * CF + j] = h;
        g_Al[row * CF + j] = l;
    }
}

// ---------------------------------------------------------------------------
// 2) inverse column norms
// ---------------------------------------------------------------------------
__global__ void __launch_bounds__(1024) k_nsq(const float* __restrict__ img) {
    int b = blockIdx.x;
    int r = threadIdx.x & 255;
    int q = threadIdx.x >> 8;
    const float* p = img + (size_t)b * CF * RR + r;
    float s = 0.f;
#pragma unroll 8
    for (int f = q * 256; f < q * 256 + 256; f++) { float v = p[(size_t)f * RR]; s += v * v; }
    __shared__ float red[1024];
    red[threadIdx.x] = s; __syncthreads();
    if (q == 0) {
        s = red[r] + red[r + 256] + red[r + 512] + red[r + 768];
        g_inorm[b * RR + r] = 1.f / fmaxf(sqrtf(s), 1e-12f);
    }
}

// ---------------------------------------------------------------------------
// 3) transpose + normalize + fp16 convert
// ---------------------------------------------------------------------------
__global__ void __launch_bounds__(256) k_bt(const float* __restrict__ img) {
    int b  = blockIdx.z;
    int k0 = blockIdx.y * 32;
    int r0 = blockIdx.x * 32;
    __shared__ float t[32][33];
    const float* src = img + (size_t)b * CF * RR;
#pragma unroll
    for (int d = 0; d < 4; d++) {
        int ky = threadIdx.y + 8 * d;
        t[ky][threadIdx.x] = src[(size_t)(k0 + ky) * RR + r0 + threadIdx.x];
    }
    __syncthreads();
#pragma unroll
    for (int d = 0; d < 4; d++) {
        int ry = threadIdx.y + 8 * d;
        int r = r0 + ry;
        float s = g_inorm[b * RR + r];
        float v = t[threadIdx.x][ry] * s;
        size_t o = ((size_t)b * RR + r) * CF + k0 + threadIdx.x;
        g_B[o] = __float2half(v);
    }
}

// ---------------------------------------------------------------------------
// 4) warp-MMA GEMM (fp16, 2-term A-split) + fused softmax-dot epilogue.
//    CTA: M=64, N=256, K chunks of 32, 3-stage cp.async pipeline, 2 CTA/SM.
//    grid (10 itiles, 128 b), 256 threads (8 warps, 2x4, warp tile 32x64).
// ---------------------------------------------------------------------------
#define KC     32
#define NCH    (CF / KC)        // 32
#define SROW   80               // KC*2 + 16B pad
#define A_H    0
#define A_L    5120             // 64*80
#define B_O    10240
#define STG    30720            // + 256*80
#define NSTAGE 3
#define SMEM_DYN (NSTAGE * STG) // 92160
#define CSTRIDE 264

__global__ void __launch_bounds__(256, 2) k_gemm_mma(float* __restrict__ out) {
    extern __shared__ __align__(128) char dsm[];
    const int tid   = threadIdx.x;
    const int wid   = tid >> 5;
    const int lane  = tid & 31;
    const int itile = blockIdx.x;
    const int b     = blockIdx.y;
    const int mw    = wid >> 2;           // 0..1
    const int nw    = wid & 3;            // 0..3

    const uint32_t sbase = smem_u32(dsm);

    const char* pAh = (const char*)g_Ah + (size_t)(itile * 64) * CF * 2;
    const char* pAl = (const char*)g_Al + (size_t)(itile * 64) * CF * 2;
    const char* pB  = (const char*)g_B  + (size_t)b * RR * CF * 2;

    const int crow = tid >> 2, cj = tid & 3;

    // ldmatrix A: 16x16 tiles (proven mapping)
    const uint32_t aoff = (uint32_t)((mw * 32 + (lane & 15)) * SROW + ((lane >> 4) << 4));
    // ldmatrix B x4 spanning two n8-blocks (proven mapping)
    const uint32_t boff = (uint32_t)((nw * 64 + ((lane >> 4) << 3) + (lane & 7)) * SROW
                                     + (((lane >> 3) & 1) << 4));

    float acc[2][8][4];
#pragma unroll
    for (int mi = 0; mi < 2; mi++)
#pragma unroll
        for (int ni = 0; ni < 8; ni++)
#pragma unroll
            for (int u = 0; u < 4; u++) acc[mi][ni][u] = 0.f;

    auto load_chunk = [&](int buf, int c) {
        const size_t kb = (size_t)c * (KC * 2);
        const uint32_t st = sbase + buf * STG;
        // A: 64 rows x 64B, hi+lo: 1 xfer each per thread
        CP_ASYNC16(st + A_H + crow * SROW + cj * 16,
                   pAh + (size_t)crow * (CF * 2) + kb + cj * 16);
        CP_ASYNC16(st + A_L + crow * SROW + cj * 16,
                   pAl + (size_t)crow * (CF * 2) + kb + cj * 16);
        // B: 256 rows x 64B: 4 xfers per thread
#pragma unroll
        for (int it = 0; it < 4; it++) {
            int row = crow + it * 64;
            CP_ASYNC16(st + B_O + row * SROW + cj * 16,
                       pB + (size_t)row * (CF * 2) + kb + cj * 16);
        }
    };

    load_chunk(0, 0); CP_COMMIT();
    load_chunk(1, 1); CP_COMMIT();

    for (int c = 0; c < NCH; c++) {
        const int buf = c % NSTAGE;
        // wait for chunk c's data (all but newest group when one is in flight)
        if (c == NCH - 1) { CP_WAIT(0); } else { CP_WAIT(1); }
        __syncthreads();   // all warps done with buffer (c+2)%3 (read at c-1)
        if (c + 2 < NCH) { load_chunk((c + 2) % NSTAGE, c + 2); CP_COMMIT(); }

        const uint32_t st = sbase + buf * STG;
#pragma unroll
        for (int ks = 0; ks < 2; ks++) {
            const uint32_t kb = ks * 32;   // 16 fp16 = 32 bytes
            uint32_t ah[2][4], al[2][4];
#pragma unroll
            for (int mi = 0; mi < 2; mi++) {
                ldsm4(ah[mi], st + A_H + aoff + mi * (16 * SROW) + kb);
                ldsm4(al[mi], st + A_L + aoff + mi * (16 * SROW) + kb);
            }
#pragma unroll
            for (int p = 0; p < 4; p++) {
                uint32_t b4[4];
                ldsm4(b4, st + B_O + boff + p * (16 * SROW) + kb);
#pragma unroll
                for (int mi = 0; mi < 2; mi++) {
                    mma_fp16(acc[mi][2 * p],     ah[mi], b4);
                    mma_fp16(acc[mi][2 * p],     al[mi], b4);
                    mma_fp16(acc[mi][2 * p + 1], ah[mi], b4 + 2);
                    mma_fp16(acc[mi][2 * p + 1], al[mi], b4 + 2);
                }
            }
        }
    }
    __syncthreads();

    // ---- epilogue: accums -> smem C[64][CSTRIDE] ----
    float* Cs = (float*)dsm;
    const int n0 = nw * 64;
#pragma unroll
    for (int mi = 0; mi < 2; mi++)
#pragma unroll
        for (int ni = 0; ni < 8; ni++) {
            int r0 = mw * 32 + mi * 16 + (lane >> 2);
            int c0 = n0 + ni * 8 + 2 * (lane & 3);
            Cs[r0 * CSTRIDE + c0]           = acc[mi][ni][0];
            Cs[r0 * CSTRIDE + c0 + 1]       = acc[mi][ni][1];
            Cs[(r0 + 8) * CSTRIDE + c0]     = acc[mi][ni][2];
            Cs[(r0 + 8) * CSTRIDE + c0 + 1] = acc[mi][ni][3];
        }
    __syncthreads();

    // ---- softmax-dot: 32 row-pairs, 4 per warp ----
#pragma unroll
    for (int pp = 0; pp < 4; pp++) {
        int p = wid * 4 + pp;                  // 0..31
        const float* r1 = Cs + (2 * p) * CSTRIDE;
        const float* r2 = Cs + (2 * p + 1) * CSTRIDE;
        float l1[8], l2[8];
        float m = -INFINITY;
#pragma unroll
        for (int u = 0; u < 8; u++) {
            int r = lane + u * 32;
            l1[u] = r1[r];
            l2[u] = r2[r];
            m = fmaxf(m, l1[u]);
        }
#pragma unroll
        for (int off = 16; off; off >>= 1)
            m = fmaxf(m, __shfl_xor_sync(0xffffffffu, m, off));
        float se = 0.f, sd = 0.f;
#pragma unroll
        for (int u = 0; u < 8; u++) {
            float e = __expf(l1[u] - m);
            se += e;
            sd += e * l2[u];
        }
#pragma unroll
        for (int off = 16; off; off >>= 1) {
            se += __shfl_xor_sync(0xffffffffu, se, off);
            sd += __shfl_xor_sync(0xffffffffu, sd, off);
        }
        int i = itile * 32 + p;
        if (lane == 0 && i < NATT) out[b * NATT + i] = sd / se;
    }
}

// ---------------------------------------------------------------------------
extern "C" void kernel_launch(void* const* d_in, const int* in_sizes, int n_in,
                              void* d_out, int out_size) {
    const float* img = (const float*)d_in[0];
    const float* V   = (const float*)d_in[1];
    const float* W1  = (const float*)d_in[2];
    const float* W2  = (const float*)d_in[3];
    float* out = (float*)d_out;

    cudaFuncSetAttribute(k_gemm_mma, cudaFuncAttributeMaxDynamicSharedMemorySize, SMEM_DYN);

    k_qp<<<dim3(40, CF / 256, 2), 256>>>(V, W1, W2);
    k_nsq<<<BB, 1024>>>(img);
    k_bt<<<dim3(RR / 32, CF / 32, BB), dim3(32, 8)>>>(img);
    k_gemm_mma<<<dim3(10, BB), 256, SMEM_DYN>>>(out);
}

// round 7
// speedup vs baseline: 1.4458x; 1.0380x over previous
#include <cuda_runtime.h>
#include <cuda_fp16.h>
#include <math.h>
#include <stdint.h>

#define BB   128
#define CF   1024
#define RR   256
#define NATT 312
#define DV   300
#define NI   624
#define NIP  640

// ---------------- scratch (device globals) ----------------
__device__ __half g_Ah[NIP * CF];              // interleaved [2i]=Q_i,[2i+1]=P_i (hi)
__device__ __half g_Al[NIP * CF];              // (lo residual)
__device__ __half g_B[(size_t)BB * RR * CF];   // [b][r][k] RAW img (transposed), fp16
__device__ float  g_part[BB * 32 * RR];        // partial sumsq [b][kc][r]
__device__ float  g_inorm[BB * RR];            // 1 / max(||img[b,:,r]||, eps)

// ---------------- helpers ----------------
__device__ __forceinline__ uint32_t smem_u32(const void* p) {
    uint32_t a;
    asm("{ .reg .u64 t; cvta.to.shared.u64 t, %1; cvt.u32.u64 %0, t; }" : "=r"(a) : "l"(p));
    return a;
}
#define CP_ASYNC16(dst, src) \
    asm volatile("cp.async.cg.shared.global [%0], [%1], 16;" :: "r"(dst), "l"(src) : "memory")
#define CP_COMMIT() asm volatile("cp.async.commit_group;" ::: "memory")
#define CP_WAIT(N)  asm volatile("cp.async.wait_group %0;" :: "n"(N) : "memory")

__device__ __forceinline__ void ldsm4(uint32_t* r, uint32_t addr) {
    asm volatile("ldmatrix.sync.aligned.m8n8.x4.shared.b16 {%0,%1,%2,%3}, [%4];"
                 : "=r"(r[0]), "=r"(r[1]), "=r"(r[2]), "=r"(r[3]) : "r"(addr));
}
__device__ __forceinline__ void mma_fp16(float* c, const uint32_t* a, const uint32_t* b) {
    asm volatile(
        "mma.sync.aligned.m16n8k16.row.col.f32.f16.f16.f32 "
        "{%0,%1,%2,%3}, {%4,%5,%6,%7}, {%8,%9}, {%0,%1,%2,%3};"
        : "+f"(c[0]), "+f"(c[1]), "+f"(c[2]), "+f"(c[3])
        : "r"(a[0]), "r"(a[1]), "r"(a[2]), "r"(a[3]), "r"(b[0]), "r"(b[1]));
}

// ---------------------------------------------------------------------------
// 1) QP rows: normalize V rows, multiply by W, interleave, fp16 hi/lo.
//    16 rows per block. grid (20, 4, 2). Rows >= NATT produce zeros (padding).
// ---------------------------------------------------------------------------
__global__ void __launch_bounds__(256) k_qp(const float* __restrict__ V,
                                            const float* __restrict__ W1,
                                            const float* __restrict__ W2) {
    int i0 = blockIdx.x * 16;
    int z  = blockIdx.z;
    int j  = blockIdx.y * 256 + threadIdx.x;
    const float* W = z ? W2 : W1;

    __shared__ float vrow[16][DV];
    for (int t = threadIdx.x; t < 16 * DV; t += 256) {
        int ii = t / DV, k = t % DV;
        int gi = i0 + ii;
        vrow[ii][k] = (gi < NATT) ? V[gi * DV + k] : 0.f;
    }
    __syncthreads();
    // warp w normalizes rows 2w, 2w+1
    {
        int w = threadIdx.x >> 5, lane = threadIdx.x & 31;
#pragma unroll
        for (int h = 0; h < 2; h++) {
            int row = 2 * w + h;
            float s = 0.f;
            for (int k = lane; k < DV; k += 32) { float v = vrow[row][k]; s += v * v; }
#pragma unroll
            for (int off = 16; off; off >>= 1) s += __shfl_xor_sync(0xffffffffu, s, off);
            float inv = 1.f / fmaxf(sqrtf(s), 1e-12f);
            for (int k = lane; k < DV; k += 32) vrow[row][k] *= inv;
        }
    }
    __syncthreads();

    float acc[16];
#pragma unroll
    for (int ii = 0; ii < 16; ii++) acc[ii] = 0.f;
    for (int k = 0; k < DV; k++) {
        float w = W[k * CF + j];
#pragma unroll
        for (int ii = 0; ii < 16; ii++) acc[ii] += vrow[ii][k] * w;
    }
#pragma unroll
    for (int ii = 0; ii < 16; ii++) {
        int row = 2 * (i0 + ii) + z;      // < NIP*2 always
        float x = acc[ii];
        __half h = __float2half(x);
        __half l = __float2half(x - __half2float(h));
        g_Ah[row * CF + j] = h;
        g_Al[row * CF + j] = l;
    }
}

// ---------------------------------------------------------------------------
// 2) Fused transpose+convert+norm-partials: ONE pass over img.
//    grid (128 b, 32 kc), block 256. Each block: img[b][k0..k0+32][0..256]
//    -> g_B[b][r][k0..k0+32] (fp16, raw) and g_part[b][kc][r] = sum_k v^2.
// ---------------------------------------------------------------------------
__global__ void __launch_bounds__(256) k_conv(const float* __restrict__ img) {
    int b  = blockIdx.x;
    int k0 = blockIdx.y * 32;
    int tid = threadIdx.x;
    __shared__ float t[32][257];
    const float* src = img + (size_t)b * CF * RR + (size_t)k0 * RR;
#pragma unroll 8
    for (int k = 0; k < 32; k++) t[k][tid] = src[k * RR + tid];
    __syncthreads();

    // partial sumsq for r = tid
    {
        float s = 0.f;
#pragma unroll
        for (int k = 0; k < 32; k++) { float v = t[k][tid]; s += v * v; }
        g_part[(b * 32 + blockIdx.y) * RR + tid] = s;
    }

    // write fp16 transposed: 256 r x 32 k halves; 8B per thread per iter
    __half* dst = g_B + ((size_t)b * RR) * CF + k0;
#pragma unroll
    for (int it = 0; it < 8; it++) {
        int idx = it * 256 + tid;      // 0..2047
        int r   = idx >> 3;            // 0..255
        int kk  = (idx & 7) * 4;       // halves kk..kk+3
        __half2 h0 = __floats2half2_rn(t[kk + 0][r], t[kk + 1][r]);
        __half2 h1 = __floats2half2_rn(t[kk + 2][r], t[kk + 3][r]);
        __half2* p = (__half2*)(dst + (size_t)r * CF + kk);
        p[0] = h0;
        p[1] = h1;
    }
}

// ---------------------------------------------------------------------------
// 3) reduce partials -> inorm. grid 128, block 256.
// ---------------------------------------------------------------------------
__global__ void __launch_bounds__(256) k_nred() {
    int b = blockIdx.x, r = threadIdx.x;
    float s = 0.f;
#pragma unroll
    for (int kc = 0; kc < 32; kc++) s += g_part[(b * 32 + kc) * RR + r];
    g_inorm[b * RR + r] = 1.f / fmaxf(sqrtf(s), 1e-12f);
}

// ---------------------------------------------------------------------------
// 4) warp-MMA GEMM (fp16, 2-term A-split) + fused scaled softmax-dot epilogue.
//    CTA: M=64, N=256, K chunks of 32, 3-stage cp.async pipeline, 2 CTA/SM.
// ---------------------------------------------------------------------------
#define KC     32
#define NCH    (CF / KC)        // 32
#define SROW   80               // KC*2 + 16B pad
#define A_H    0
#define A_L    5120             // 64*80
#define B_O    10240
#define STG    30720            // + 256*80
#define NSTAGE 3
#define SMEM_DYN (NSTAGE * STG) // 92160
#define CSTRIDE 264

__global__ void __launch_bounds__(256, 2) k_gemm_mma(float* __restrict__ out) {
    extern __shared__ __align__(128) char dsm[];
    const int tid   = threadIdx.x;
    const int wid   = tid >> 5;
    const int lane  = tid & 31;
    const int itile = blockIdx.x;
    const int b     = blockIdx.y;
    const int mw    = wid >> 2;           // 0..1
    const int nw    = wid & 3;            // 0..3

    const uint32_t sbase = smem_u32(dsm);

    const char* pAh = (const char*)g_Ah + (size_t)(itile * 64) * CF * 2;
    const char* pAl = (const char*)g_Al + (size_t)(itile * 64) * CF * 2;
    const char* pB  = (const char*)g_B  + (size_t)b * RR * CF * 2;

    const int crow = tid >> 2, cj = tid & 3;

    const uint32_t aoff = (uint32_t)((mw * 32 + (lane & 15)) * SROW + ((lane >> 4) << 4));
    const uint32_t boff = (uint32_t)((nw * 64 + ((lane >> 4) << 3) + (lane & 7)) * SROW
                                     + (((lane >> 3) & 1) << 4));

    float acc[2][8][4];
#pragma unroll
    for (int mi = 0; mi < 2; mi++)
#pragma unroll
        for (int ni = 0; ni < 8; ni++)
#pragma unroll
            for (int u = 0; u < 4; u++) acc[mi][ni][u] = 0.f;

    auto load_chunk = [&](int buf, int c) {
        const size_t kb = (size_t)c * (KC * 2);
        const uint32_t st = sbase + buf * STG;
        CP_ASYNC16(st + A_H + crow * SROW + cj * 16,
                   pAh + (size_t)crow * (CF * 2) + kb + cj * 16);
        CP_ASYNC16(st + A_L + crow * SROW + cj * 16,
                   pAl + (size_t)crow * (CF * 2) + kb + cj * 16);
#pragma unroll
        for (int it = 0; it < 4; it++) {
            int row = crow + it * 64;
            CP_ASYNC16(st + B_O + row * SROW + cj * 16,
                       pB + (size_t)row * (CF * 2) + kb + cj * 16);
        }
    };

    load_chunk(0, 0); CP_COMMIT();
    load_chunk(1, 1); CP_COMMIT();

    for (int c = 0; c < NCH; c++) {
        const int buf = c % NSTAGE;
        if (c == NCH - 1) { CP_WAIT(0); } else { CP_WAIT(1); }
        __syncthreads();
        if (c + 2 < NCH) { load_chunk((c + 2) % NSTAGE, c + 2); CP_COMMIT(); }

        const uint32_t st = sbase + buf * STG;
#pragma unroll
        for (int ks = 0; ks < 2; ks++) {
            const uint32_t kb = ks * 32;
            uint32_t ah[2][4], al[2][4];
#pragma unroll
            for (int mi = 0; mi < 2; mi++) {
                ldsm4(ah[mi], st + A_H + aoff + mi * (16 * SROW) + kb);
                ldsm4(al[mi], st + A_L + aoff + mi * (16 * SROW) + kb);
            }
#pragma unroll
            for (int p = 0; p < 4; p++) {
                uint32_t b4[4];
                ldsm4(b4, st + B_O + boff + p * (16 * SROW) + kb);
#pragma unroll
                for (int mi = 0; mi < 2; mi++) {
                    mma_fp16(acc[mi][2 * p],     ah[mi], b4);
                    mma_fp16(acc[mi][2 * p],     al[mi], b4);
                    mma_fp16(acc[mi][2 * p + 1], ah[mi], b4 + 2);
                    mma_fp16(acc[mi][2 * p + 1], al[mi], b4 + 2);
                }
            }
        }
    }
    __syncthreads();

    // ---- epilogue: accums -> smem C[64][CSTRIDE] ----
    float* Cs = (float*)dsm;
    const int n0 = nw * 64;
#pragma unroll
    for (int mi = 0; mi < 2; mi++)
#pragma unroll
        for (int ni = 0; ni < 8; ni++) {
            int r0 = mw * 32 + mi * 16 + (lane >> 2);
            int c0 = n0 + ni * 8 + 2 * (lane & 3);
            Cs[r0 * CSTRIDE + c0]           = acc[mi][ni][0];
            Cs[r0 * CSTRIDE + c0 + 1]       = acc[mi][ni][1];
            Cs[(r0 + 8) * CSTRIDE + c0]     = acc[mi][ni][2];
            Cs[(r0 + 8) * CSTRIDE + c0 + 1] = acc[mi][ni][3];
        }
    __syncthreads();

    // ---- scaled softmax-dot: 32 row-pairs, 4 per warp ----
    float sn[8];
#pragma unroll
    for (int u = 0; u < 8; u++) sn[u] = g_inorm[b * RR + lane + u * 32];

#pragma unroll
    for (int pp = 0; pp < 4; pp++) {
        int p = wid * 4 + pp;
        const float* r1 = Cs + (2 * p) * CSTRIDE;
        const float* r2 = Cs + (2 * p + 1) * CSTRIDE;
        float l1[8], l2[8];
        float m = -INFINITY;
#pragma unroll
        for (int u = 0; u < 8; u++) {
            int r = lane + u * 32;
            l1[u] = r1[r] * sn[u];
            l2[u] = r2[r] * sn[u];
            m = fmaxf(m, l1[u]);
        }
#pragma unroll
        for (int off = 16; off; off >>= 1)
            m = fmaxf(m, __shfl_xor_sync(0xffffffffu, m, off));
        float se = 0.f, sd = 0.f;
#pragma unroll
        for (int u = 0; u < 8; u++) {
            float e = __expf(l1[u] - m);
            se += e;
            sd += e * l2[u];
        }
#pragma unroll
        for (int off = 16; off; off >>= 1) {
            se += __shfl_xor_sync(0xffffffffu, se, off);
            sd += __shfl_xor_sync(0xffffffffu, sd, off);
        }
        int i = itile * 32 + p;
        if (lane == 0 && i < NATT) out[b * NATT + i] = sd / se;
    }
}

// ---------------------------------------------------------------------------
extern "C" void kernel_launch(void* const* d_in, const int* in_sizes, int n_in,
                              void* d_out, int out_size) {
    const float* img = (const float*)d_in[0];
    const float* V   = (const float*)d_in[1];
    const float* W1  = (const float*)d_in[2];
    const float* W2  = (const float*)d_in[3];
    float* out = (float*)d_out;

    cudaFuncSetAttribute(k_gemm_mma, cudaFuncAttributeMaxDynamicSharedMemorySize, SMEM_DYN);

    k_qp<<<dim3(20, CF / 256, 2), 256>>>(V, W1, W2);
    k_conv<<<dim3(BB, 32), 256>>>(img);
    k_nred<<<BB, RR>>>();
    k_gemm_mma<<<dim3(10, BB), 256, SMEM_DYN>>>(out);
}

// round 8
// speedup vs baseline: 1.9667x; 1.3603x over previous
#include <cuda_runtime.h>
#include <cuda_fp16.h>
#include <math.h>
#include <stdint.h>

#define BB   128
#define CF   1024
#define RR   256
#define NATT 312
#define DV   300
#define NI   624
#define NIP  640

// ---------------- scratch (device globals) ----------------
__device__ __half g_A[NIP * CF];               // interleaved [2i]=Q_i,[2i+1]=P_i
__device__ __half g_B[(size_t)BB * RR * CF];   // [b][r][k] RAW img (transposed), fp16
__device__ float  g_part[BB * 32 * RR];        // partial sumsq [b][kc][r]
__device__ float  g_inorm[BB * RR];            // 1 / max(||img[b,:,r]||, eps)

// ---------------- helpers ----------------
__device__ __forceinline__ uint32_t smem_u32(const void* p) {
    uint32_t a;
    asm("{ .reg .u64 t; cvta.to.shared.u64 t, %1; cvt.u32.u64 %0, t; }" : "=r"(a) : "l"(p));
    return a;
}
#define CP_ASYNC16(dst, src) \
    asm volatile("cp.async.cg.shared.global [%0], [%1], 16;" :: "r"(dst), "l"(src) : "memory")
#define CP_COMMIT() asm volatile("cp.async.commit_group;" ::: "memory")
#define CP_WAIT(N)  asm volatile("cp.async.wait_group %0;" :: "n"(N) : "memory")

__device__ __forceinline__ void ldsm4(uint32_t* r, uint32_t addr) {
    asm volatile("ldmatrix.sync.aligned.m8n8.x4.shared.b16 {%0,%1,%2,%3}, [%4];"
                 : "=r"(r[0]), "=r"(r[1]), "=r"(r[2]), "=r"(r[3]) : "r"(addr));
}
__device__ __forceinline__ void mma_fp16(float* c, const uint32_t* a, const uint32_t* b) {
    asm volatile(
        "mma.sync.aligned.m16n8k16.row.col.f32.f16.f16.f32 "
        "{%0,%1,%2,%3}, {%4,%5,%6,%7}, {%8,%9}, {%0,%1,%2,%3};"
        : "+f"(c[0]), "+f"(c[1]), "+f"(c[2]), "+f"(c[3])
        : "r"(a[0]), "r"(a[1]), "r"(a[2]), "r"(a[3]), "r"(b[0]), "r"(b[1]));
}

// ---------------------------------------------------------------------------
// 1) QP rows: normalize V rows, multiply by W, interleave, single fp16.
//    16 rows per block. grid (20, 4, 2). Rows >= NATT produce zeros (padding).
// ---------------------------------------------------------------------------
__global__ void __launch_bounds__(256) k_qp(const float* __restrict__ V,
                                            const float* __restrict__ W1,
                                            const float* __restrict__ W2) {
    int i0 = blockIdx.x * 16;
    int z  = blockIdx.z;
    int j  = blockIdx.y * 256 + threadIdx.x;
    const float* W = z ? W2 : W1;

    __shared__ float vrow[16][DV];
    for (int t = threadIdx.x; t < 16 * DV; t += 256) {
        int ii = t / DV, k = t % DV;
        int gi = i0 + ii;
        vrow[ii][k] = (gi < NATT) ? V[gi * DV + k] : 0.f;
    }
    __syncthreads();
    {
        int w = threadIdx.x >> 5, lane = threadIdx.x & 31;
#pragma unroll
        for (int h = 0; h < 2; h++) {
            int row = 2 * w + h;
            float s = 0.f;
            for (int k = lane; k < DV; k += 32) { float v = vrow[row][k]; s += v * v; }
#pragma unroll
            for (int off = 16; off; off >>= 1) s += __shfl_xor_sync(0xffffffffu, s, off);
            float inv = 1.f / fmaxf(sqrtf(s), 1e-12f);
            for (int k = lane; k < DV; k += 32) vrow[row][k] *= inv;
        }
    }
    __syncthreads();

    float acc[16];
#pragma unroll
    for (int ii = 0; ii < 16; ii++) acc[ii] = 0.f;
    for (int k = 0; k < DV; k++) {
        float w = W[k * CF + j];
#pragma unroll
        for (int ii = 0; ii < 16; ii++) acc[ii] += vrow[ii][k] * w;
    }
#pragma unroll
    for (int ii = 0; ii < 16; ii++) {
        int row = 2 * (i0 + ii) + z;
        g_A[row * CF + j] = __float2half(acc[ii]);
    }
}

// ---------------------------------------------------------------------------
// 2) Fused transpose+convert+norm-partials: ONE pass over img.
// ---------------------------------------------------------------------------
__global__ void __launch_bounds__(256) k_conv(const float* __restrict__ img) {
    int b  = blockIdx.x;
    int k0 = blockIdx.y * 32;
    int tid = threadIdx.x;
    __shared__ float t[32][257];
    const float* src = img + (size_t)b * CF * RR + (size_t)k0 * RR;
#pragma unroll 8
    for (int k = 0; k < 32; k++) t[k][tid] = src[k * RR + tid];
    __syncthreads();

    {
        float s = 0.f;
#pragma unroll
        for (int k = 0; k < 32; k++) { float v = t[k][tid]; s += v * v; }
        g_part[(b * 32 + blockIdx.y) * RR + tid] = s;
    }

    __half* dst = g_B + ((size_t)b * RR) * CF + k0;
#pragma unroll
    for (int it = 0; it < 8; it++) {
        int idx = it * 256 + tid;
        int r   = idx >> 3;
        int kk  = (idx & 7) * 4;
        __half2 h0 = __floats2half2_rn(t[kk + 0][r], t[kk + 1][r]);
        __half2 h1 = __floats2half2_rn(t[kk + 2][r], t[kk + 3][r]);
        __half2* p = (__half2*)(dst + (size_t)r * CF + kk);
        p[0] = h0;
        p[1] = h1;
    }
}

// ---------------------------------------------------------------------------
// 3) reduce partials -> inorm
// ---------------------------------------------------------------------------
__global__ void __launch_bounds__(256) k_nred() {
    int b = blockIdx.x, r = threadIdx.x;
    float s = 0.f;
#pragma unroll
    for (int kc = 0; kc < 32; kc++) s += g_part[(b * 32 + kc) * RR + r];
    g_inorm[b * RR + r] = 1.f / fmaxf(sqrtf(s), 1e-12f);
}

// ---------------------------------------------------------------------------
// 4) warp-MMA GEMM (single-term fp16) + fused scaled softmax-dot epilogue.
//    CTA: M=64, N=256, K chunks of 64, 2-stage cp.async double buffer,
//    2 CTA/SM. grid (10 itiles, 128 b), 256 threads (8 warps, warp 32x64).
// ---------------------------------------------------------------------------
#define KC     64
#define NCH    (CF / KC)        // 16
#define SROW   144              // KC*2 + 16B pad
#define A_O    0
#define B_O    9216             // 64*144
#define STG    46080            // + 256*144
#define NSTAGE 2
#define SMEM_DYN (NSTAGE * STG) // 92160
#define CSTRIDE 264

__global__ void __launch_bounds__(256, 2) k_gemm_mma(float* __restrict__ out) {
    extern __shared__ __align__(128) char dsm[];
    const int tid   = threadIdx.x;
    const int wid   = tid >> 5;
    const int lane  = tid & 31;
    const int itile = blockIdx.x;
    const int b     = blockIdx.y;
    const int mw    = wid >> 2;           // 0..1
    const int nw    = wid & 3;            // 0..3

    const uint32_t sbase = smem_u32(dsm);

    const char* pA = (const char*)g_A + (size_t)(itile * 64) * CF * 2;
    const char* pB = (const char*)g_B + (size_t)b * RR * CF * 2;

    const uint32_t aoff = (uint32_t)((mw * 32 + (lane & 15)) * SROW + ((lane >> 4) << 4));
    const uint32_t boff = (uint32_t)((nw * 64 + ((lane >> 4) << 3) + (lane & 7)) * SROW
                                     + (((lane >> 3) & 1) << 4));

    float acc[2][8][4];
#pragma unroll
    for (int mi = 0; mi < 2; mi++)
#pragma unroll
        for (int ni = 0; ni < 8; ni++)
#pragma unroll
            for (int u = 0; u < 4; u++) acc[mi][ni][u] = 0.f;

    auto load_chunk = [&](int buf, int c) {
        const size_t kb = (size_t)c * (KC * 2);
        const uint32_t st = sbase + buf * STG;
        // A: 64 rows x 128B = 512 xfers (2/thread)
#pragma unroll
        for (int it = 0; it < 2; it++) {
            int idx = tid + it * 256;
            int row = idx >> 3, j = idx & 7;
            CP_ASYNC16(st + A_O + row * SROW + j * 16,
                       pA + (size_t)row * (CF * 2) + kb + j * 16);
        }
        // B: 256 rows x 128B = 2048 xfers (8/thread)
#pragma unroll
        for (int it = 0; it < 8; it++) {
            int idx = tid + it * 256;
            int row = idx >> 3, j = idx & 7;
            CP_ASYNC16(st + B_O + row * SROW + j * 16,
                       pB + (size_t)row * (CF * 2) + kb + j * 16);
        }
    };

    load_chunk(0, 0); CP_COMMIT();

    for (int c = 0; c < NCH; c++) {
        const int buf = c & 1;
        CP_WAIT(0);            // chunk c arrived (only group in flight)
        __syncthreads();       // all warps done computing chunk c-1 (buffer buf^1)
        if (c + 1 < NCH) { load_chunk(buf ^ 1, c + 1); CP_COMMIT(); }

        const uint32_t st = sbase + buf * STG;
#pragma unroll
        for (int ks = 0; ks < 4; ks++) {
            const uint32_t kb = ks * 32;   // 16 fp16 = 32 bytes
            uint32_t a4[2][4];
#pragma unroll
            for (int mi = 0; mi < 2; mi++)
                ldsm4(a4[mi], st + A_O + aoff + mi * (16 * SROW) + kb);
#pragma unroll
            for (int p = 0; p < 4; p++) {
                uint32_t b4[4];
                ldsm4(b4, st + B_O + boff + p * (16 * SROW) + kb);
#pragma unroll
                for (int mi = 0; mi < 2; mi++) {
                    mma_fp16(acc[mi][2 * p],     a4[mi], b4);
                    mma_fp16(acc[mi][2 * p + 1], a4[mi], b4 + 2);
                }
            }
        }
    }
    __syncthreads();

    // ---- epilogue: accums -> smem C[64][CSTRIDE] ----
    float* Cs = (float*)dsm;
    const int n0 = nw * 64;
#pragma unroll
    for (int mi = 0; mi < 2; mi++)
#pragma unroll
        for (int ni = 0; ni < 8; ni++) {
            int r0 = mw * 32 + mi * 16 + (lane >> 2);
            int c0 = n0 + ni * 8 + 2 * (lane & 3);
            Cs[r0 * CSTRIDE + c0]           = acc[mi][ni][0];
            Cs[r0 * CSTRIDE + c0 + 1]       = acc[mi][ni][1];
            Cs[(r0 + 8) * CSTRIDE + c0]     = acc[mi][ni][2];
            Cs[(r0 + 8) * CSTRIDE + c0 + 1] = acc[mi][ni][3];
        }
    __syncthreads();

    // ---- scaled softmax-dot: 32 row-pairs, 4 per warp ----
    float sn[8];
#pragma unroll
    for (int u = 0; u < 8; u++) sn[u] = g_inorm[b * RR + lane + u * 32];

#pragma unroll
    for (int pp = 0; pp < 4; pp++) {
        int p = wid * 4 + pp;
        const float* r1 = Cs + (2 * p) * CSTRIDE;
        const float* r2 = Cs + (2 * p + 1) * CSTRIDE;
        float l1[8], l2[8];
        float m = -INFINITY;
#pragma unroll
        for (int u = 0; u < 8; u++) {
            int r = lane + u * 32;
            l1[u] = r1[r] * sn[u];
            l2[u] = r2[r] * sn[u];
            m = fmaxf(m, l1[u]);
        }
#pragma unroll
        for (int off = 16; off; off >>= 1)
            m = fmaxf(m, __shfl_xor_sync(0xffffffffu, m, off));
        float se = 0.f, sd = 0.f;
#pragma unroll
        for (int u = 0; u < 8; u++) {
            float e = __expf(l1[u] - m);
            se += e;
            sd += e * l2[u];
        }
#pragma unroll
        for (int off = 16; off; off >>= 1) {
            se += __shfl_xor_sync(0xffffffffu, se, off);
            sd += __shfl_xor_sync(0xffffffffu, sd, off);
        }
        int i = itile * 32 + p;
        if (lane == 0 && i < NATT) out[b * NATT + i] = sd / se;
    }
}

// ---------------------------------------------------------------------------
extern "C" void kernel_launch(void* const* d_in, const int* in_sizes, int n_in,
                              void* d_out, int out_size) {
    const float* img = (const float*)d_in[0];
    const float* V   = (const float*)d_in[1];
    const float* W1  = (const float*)d_in[2];
    const float* W2  = (const float*)d_in[3];
    float* out = (float*)d_out;

    cudaFuncSetAttribute(k_gemm_mma, cudaFuncAttributeMaxDynamicSharedMemorySize, SMEM_DYN);

    k_qp<<<dim3(20, CF / 256, 2), 256>>>(V, W1, W2);
    k_conv<<<dim3(BB, 32), 256>>>(img);
    k_nred<<<BB, RR>>>();
    k_gemm_mma<<<dim3(10, BB), 256, SMEM_DYN>>>(out);
}